// round 15
// baseline (speedup 1.0000x reference)
#include <cuda_runtime.h>
#include <cstdint>
#include <cmath>

// Problem constants (fixed by the reference)
constexpr int B  = 4;
constexpr int C  = 32;
constexpr int GW = 64;               // W = L = H = 64
constexpr int LH = GW * GW;          // 4096
constexpr int V  = GW * GW * GW;     // 262144
constexpr int BV = B * V;            // 1,048,576 = 256 * 4096
constexpr int NMAX = 200000;
constexpr unsigned MIN_PTS = 10;
constexpr int SCAN_BLOCKS = 256;     // each scans 4096 counts (1024 thr x uint4)

// Static scratch (no allocations allowed). Accessed ONLY from device code.
// g_counts and g_scan_status rely on the zero-at-module-load invariant:
// scan re-zeroes g_counts right after consuming it; gather re-zeroes
// g_scan_status. Both restored every launch -> graph-replay deterministic.
__device__ __align__(128) float g_csr[(size_t)B * NMAX * C]; // CSR-ordered attr lines
__device__ int      g_vox        [B * NMAX];        // flat voxel id (b*V+v) or -1
__device__ unsigned g_counts     [BV];              // per-voxel point counts
__device__ unsigned g_cursor     [BV];              // excl. offsets -> CSR end cursor
__device__ unsigned g_scan_status[SCAN_BLOCKS];     // lookback: (value<<2)|state

// ---------------------------------------------------------------------------
// K1: voxelize + histogram. Match XLA: (p-0)/0.05 folded to p * 20.0f
// (f32-rounded reciprocal is exactly 20.0f), separate rn-mul / rn-add.
// ---------------------------------------------------------------------------
__device__ __forceinline__ int voxelize(float p) {
    return (int)floorf(__fadd_rn(__fmul_rn(p, 20.0f), 0.5f));
}

__global__ void voxelize_count_kernel(const float* __restrict__ coords, int N) {
    int n = blockIdx.x * blockDim.x + threadIdx.x;
    int b = blockIdx.y;
    if (n >= N) return;

    const float* cb = coords + (size_t)b * 3 * N;
    int x = voxelize(cb[n]);
    int y = voxelize(cb[(size_t)N + n]);
    int z = voxelize(cb[(size_t)2 * N + n]);

    int bv = -1;
    if ((unsigned)x < (unsigned)GW && (unsigned)y < (unsigned)GW &&
        (unsigned)z < (unsigned)GW) {
        bv = b * V + x * LH + y * GW + z;
        atomicAdd(&g_counts[bv], 1u);
    }
    g_vox[b * NMAX + n] = bv;
}

// ---------------------------------------------------------------------------
// Block-level exclusive scan helper (1024 threads, 32 warps).
// ---------------------------------------------------------------------------
__device__ __forceinline__ unsigned block_exclusive_scan(unsigned v, unsigned* total) {
    __shared__ unsigned wsum[32];
    int tid  = threadIdx.x;
    int lane = tid & 31, wid = tid >> 5;

    unsigned x = v;
    #pragma unroll
    for (int d = 1; d < 32; d <<= 1) {
        unsigned t = __shfl_up_sync(0xffffffffu, x, d);
        if (lane >= d) x += t;
    }
    if (lane == 31) wsum[wid] = x;
    __syncthreads();
    if (wid == 0) {
        unsigned s = wsum[lane];
        #pragma unroll
        for (int d = 1; d < 32; d <<= 1) {
            unsigned t = __shfl_up_sync(0xffffffffu, s, d);
            if (lane >= d) s += t;
        }
        wsum[lane] = s;                    // inclusive warp-total prefix
    }
    __syncthreads();
    unsigned wp = (wid > 0) ? wsum[wid - 1] : 0u;
    *total = wsum[31];
    return wp + x - v;                     // exclusive prefix
}

// ---------------------------------------------------------------------------
// K2: single-pass scan with decoupled lookback. Writes GLOBAL exclusive
// prefixes of g_counts straight into g_cursor (uint4 per thread), and
// restores g_counts' zero-invariant (counts live in registers here).
// Status word: (value << 2) | state; state 1 = aggregate, 2 = inclusive
// prefix. Totals < 2^20 so the shift is safe. All 256 blocks co-resident
// (2 blocks/SM x 148 SMs = 296 slots), so the spin cannot deadlock.
// ---------------------------------------------------------------------------
__global__ void scan_cursor_kernel() {
    __shared__ unsigned s_prefix;
    int tid = threadIdx.x;
    int blk = blockIdx.x;
    int i4  = blk * 1024 + tid;                      // uint4 index, BV/4 total

    uint4 c = reinterpret_cast<const uint4*>(g_counts)[i4];
    reinterpret_cast<uint4*>(g_counts)[i4] = make_uint4(0u, 0u, 0u, 0u);
    unsigned tsum = c.x + c.y + c.z + c.w;

    unsigned total;
    unsigned ex = block_exclusive_scan(tsum, &total);

    if (tid == 0) {
        if (blk == 0) {
            atomicExch(&g_scan_status[0], (total << 2) | 2u);
            s_prefix = 0u;
        } else {
            atomicExch(&g_scan_status[blk], (total << 2) | 1u);
            unsigned p = 0u;
            int i = blk - 1;
            while (true) {
                unsigned s = atomicAdd(&g_scan_status[i], 0u);  // gpu-scope read
                unsigned st = s & 3u;
                if (st == 0u) continue;                // not published yet
                p += s >> 2;
                if (st == 2u) break;                   // hit a full prefix
                --i;
            }
            atomicExch(&g_scan_status[blk], ((p + total) << 2) | 2u);
            s_prefix = p;
        }
    }
    __syncthreads();

    unsigned p = s_prefix;
    uint4 o;
    o.x = ex + p;
    o.y = o.x + c.x;
    o.z = o.y + c.y;
    o.w = o.z + c.z;
    reinterpret_cast<uint4*>(g_cursor)[i4] = o;
}

// ---------------------------------------------------------------------------
// K3: scatter attribute lines into CSR order. One thread per point.
// Reads attrs [B][C][N] coalesced across lanes (fixed c, consecutive n);
// writes one contiguous 128B line per point at its CSR slot.
// ---------------------------------------------------------------------------
__global__ void scatter_csr_kernel(const float* __restrict__ attrs, int N) {
    int n = blockIdx.x * blockDim.x + threadIdx.x;
    int b = blockIdx.y;
    if (n >= N) return;
    int bv = g_vox[b * NMAX + n];
    if (bv < 0) return;

    unsigned pos = atomicAdd(&g_cursor[bv], 1u);

    const float* ab = attrs + (size_t)b * C * N + n;
    float v[C];
    #pragma unroll
    for (int c = 0; c < C; c++) v[c] = ab[(size_t)c * N];   // coalesced

    float4* dst = reinterpret_cast<float4*>(g_csr + (size_t)pos * C);
    #pragma unroll
    for (int j = 0; j < C / 4; j++)
        dst[j] = make_float4(v[4*j], v[4*j+1], v[4*j+2], v[4*j+3]);
}

// ---------------------------------------------------------------------------
// K4: gather max per voxel (warp lanes = channels). Each warp owns 4 voxels
// INTERLEAVED (4 independent predicated line-loads per step -> MLP=4; outer
// trips = max of the 4 counts). Counts & starts come from CURSOR DIFFS:
// after K3, g_cursor[bv] == end(bv) and end(bv-1) == start(bv) (global
// inclusive prefix), so one 33-entry smem stage supplies both. No g_counts
// access. Pointer-increment inner loop (no per-iter index arithmetic).
// Block (0,0) restores g_scan_status's zero-invariant.
// ---------------------------------------------------------------------------
__global__ void gather_finalize_kernel(float* __restrict__ out,
                                       float* __restrict__ occ) {
    __shared__ float    tile[32][C + 1];
    __shared__ unsigned send[33];                    // send[i] = start of voxel v0+i

    int b   = blockIdx.y;
    int v0  = blockIdx.x * 32;
    int bv0 = b * V + v0;
    int tx  = threadIdx.x, ty = threadIdx.y;         // (32, 8)

    if (ty == 0) send[1 + tx] = g_cursor[bv0 + tx];  // end(bv0+tx)
    if (ty == 1 && tx == 0)
        send[0] = (bv0 > 0) ? g_cursor[bv0 - 1] : 0u;
    if (blockIdx.x == 0 && b == 0 && ty == 2) g_scan_status[tx] = 0u;
    if (blockIdx.x == 0 && b == 0 && ty == 3) g_scan_status[32 + tx] = 0u;
    if (blockIdx.x == 0 && b == 0 && ty == 4) g_scan_status[64 + tx] = 0u;
    if (blockIdx.x == 0 && b == 0 && ty == 5) g_scan_status[96 + tx] = 0u;
    if (blockIdx.x == 0 && b == 0 && ty == 6) g_scan_status[128 + tx] = 0u;
    if (blockIdx.x == 0 && b == 0 && ty == 7) g_scan_status[160 + tx] = 0u;
    if (blockIdx.x == 1 && b == 0 && ty == 2) g_scan_status[192 + tx] = 0u;
    if (blockIdx.x == 1 && b == 0 && ty == 3) g_scan_status[224 + tx] = 0u;
    __syncthreads();

    // occupancy straight from cursor diffs (any one warp)
    if (ty == 1)
        occ[bv0 + tx] = ((send[1 + tx] - send[tx]) >= MIN_PTS) ? 1.0f : 0.0f;

    unsigned cnt[4];
    const float* p[4];
    float m[4];
    unsigned maxc = 0;
    #pragma unroll
    for (int k = 0; k < 4; k++) {
        int vl = ty + 8 * k;
        unsigned st = send[vl];
        cnt[k] = send[vl + 1] - st;
        p[k]   = g_csr + (size_t)st * C + tx;
        m[k]   = -INFINITY;
        maxc   = (cnt[k] > maxc) ? cnt[k] : maxc;
    }

    for (unsigned i = 0; i < maxc; i++) {
        #pragma unroll
        for (int k = 0; k < 4; k++) {
            if (i < cnt[k])                           // predicated, independent
                m[k] = fmaxf(m[k], *p[k]);
            p[k] += C;                                // pointer walk, no IMAD chain
        }
    }

    #pragma unroll
    for (int k = 0; k < 4; k++)
        tile[ty + 8 * k][tx] = (cnt[k] > 0u) ? m[k] : 0.0f;
    __syncthreads();

    float* ob = out + (size_t)b * C * V + v0;
    #pragma unroll
    for (int j = 0; j < 4; j++) {
        int c = ty + 8 * j;
        ob[(size_t)c * V + tx] = tile[tx][c];        // coalesced over v
    }
}

// ---------------------------------------------------------------------------
// Launch: d_out = [voxeldata (B*C*V f32)][occupancy (B*V f32)]
// ---------------------------------------------------------------------------
extern "C" void kernel_launch(void* const* d_in, const int* in_sizes, int n_in,
                              void* d_out, int out_size) {
    const float* coords = (const float*)d_in[0];   // [B,3,N]
    const float* attrs  = (const float*)d_in[1];   // [B,C,N]
    int N = in_sizes[0] / (B * 3);                 // 200000

    float* voxeldata = (float*)d_out;
    float* occ       = (float*)d_out + (size_t)B * C * V;

    dim3 vg((N + 255) / 256, B);
    voxelize_count_kernel<<<vg, 256>>>(coords, N);

    scan_cursor_kernel<<<SCAN_BLOCKS, 1024>>>();

    scatter_csr_kernel<<<vg, 256>>>(attrs, N);

    dim3 fb(32, 8);
    dim3 fg(V / 32, B);
    gather_finalize_kernel<<<fg, fb>>>(voxeldata, occ);
}